// round 15
// baseline (speedup 1.0000x reference)
#include <cuda_runtime.h>
#include <cstdint>

// ---------------------------------------------------------------------------
// edge_aggregation (B=4, E=8000, N=2000, D=256, HID=128, T=5)
// tf32 mma.sync.m16n8k8 + cp.async 2-stage pipeline + ldmatrix fragments.
// Round 15: __launch_bounds__(256,4) -> 4 CTAs/SM (64-reg cap; smem
// 55.3KB x 4 = 216KB <= 228KB). Everything else identical to round 14.
//   edges = H @ ori                      GEMM1  M=8000 N=256 K=2000  x4
//   htcat[:,t*128:+128] = relu(edges@W1_t+b1_t)*gate_t    MLP1 (1 launch, z=t)
//   ef    = htcat @ W2cat + sum_t gate_t*b2_t             MLP2 (1 launch, K=640)
//   out[:, :256] = H^T @ ef              GEMM3  M=2000 N=256 K=8000  split-K x4
//   out[:, 256:] = ori
// ---------------------------------------------------------------------------

__device__ uint32_t g_oriT[4 * 256 * 2000];      // [b][d][n] tf32
__device__ uint32_t g_W1T[5 * 128 * 256];        // [t][h][d] tf32
__device__ uint32_t g_W2cat[256 * 640];          // [d][t*128+h] tf32
__device__ uint32_t g_edges[32000 * 256];        // tf32 (GEMM1 out)
__device__ uint32_t g_htcat[32000L * 640];       // tf32 (MLP1 out, gated, concat-K)
__device__ float    g_ef[32000 * 256];           // fp32 (MLP2 out)
__device__ uint32_t g_efT[4 * 256 * 8000];       // [b][d][e] tf32
__device__ float    g_part[4L * 4 * 2000 * 256]; // split-K partials

// ---------------- PTX helpers ----------------
__device__ __forceinline__ uint32_t smem_u32(const void* p) {
    uint32_t a;
    asm("{ .reg .u64 t; cvta.to.shared.u64 t, %1; cvt.u32.u64 %0, t; }"
        : "=r"(a) : "l"(p));
    return a;
}
__device__ __forceinline__ void cpasync16(uint32_t dst, const void* src, uint32_t sz) {
    asm volatile("cp.async.cg.shared.global [%0], [%1], 16, %2;"
                 :: "r"(dst), "l"(src), "r"(sz) : "memory");
}
#define CP_COMMIT() asm volatile("cp.async.commit_group;" ::: "memory")
#define CP_WAIT1()  asm volatile("cp.async.wait_group 1;" ::: "memory")

__device__ __forceinline__ uint32_t lds32(uint32_t a) {
    uint32_t v;
    asm volatile("ld.shared.b32 %0, [%1];" : "=r"(v) : "r"(a));
    return v;
}
__device__ __forceinline__ void ldsm_x4(uint32_t (&r)[4], uint32_t a) {
    asm volatile("ldmatrix.sync.aligned.m8n8.x4.shared.b16 {%0,%1,%2,%3}, [%4];"
                 : "=r"(r[0]), "=r"(r[1]), "=r"(r[2]), "=r"(r[3]) : "r"(a));
}
__device__ __forceinline__ uint32_t f2tf32(float x) {
    uint32_t r;
    asm("cvt.rna.tf32.f32 %0, %1;" : "=r"(r) : "f"(x));
    return r;
}
__device__ __forceinline__ void mma_tf32(float (&c)[4], const uint32_t (&a)[4],
                                         uint32_t b0, uint32_t b1) {
    asm volatile(
        "mma.sync.aligned.m16n8k8.row.col.f32.tf32.tf32.f32 "
        "{%0,%1,%2,%3}, {%4,%5,%6,%7}, {%8,%9}, {%0,%1,%2,%3};"
        : "+f"(c[0]), "+f"(c[1]), "+f"(c[2]), "+f"(c[3])
        : "r"(a[0]), "r"(a[1]), "r"(a[2]), "r"(a[3]), "r"(b0), "r"(b1));
}

// ---------------------------------------------------------------------------
// Tile 64x128, K-chunk 32, 256 threads (8 warps: 2M x 4N, 32x32 per warp).
// 2-stage pipeline, 55KB smem/CTA, __launch_bounds__(256,4) -> 4 CTAs/SM.
// Tail iterations commit an empty cp.async group (round-11 race fix).
// EPI 0: C=acc
// EPI 3: C=relu(acc+bias[z])*gate[r*gld+zb]         (MLP1, OUT_TF32)
// EPI 4: C=acc + sum_t gate[r*5+t]*bias[t*256+col]  (fused MLP2, fp32 out)
// ---------------------------------------------------------------------------
template <int EPI, bool TRANS_A, bool A_CVT, bool OUT_TF32>
__global__ __launch_bounds__(256, 4)
void gemm_tf32(const uint32_t* __restrict__ A, const uint32_t* __restrict__ BT,
               void* __restrict__ Cv, int M, int N, int K,
               long sA, long sB, long sC,
               long aSplit, long bSplit, long cSplit, int nz,
               int lda, int ldb, int ldc,
               const float* __restrict__ bias, long biasZ,
               const float* __restrict__ gate, int gld)
{
    constexpr int AS_BYTES = TRANS_A ? 32 * 272 : 64 * 144;
    constexpr int BS_BYTES = 128 * 144;

    extern __shared__ __align__(16) char dyn[];
    const uint32_t as0 = smem_u32(dyn);
    const uint32_t bs0 = as0 + 2 * AS_BYTES;

    const int tid = threadIdx.x;
    const int warp = tid >> 5, lane = tid & 31;
    const int wm = warp & 1, wn = warp >> 1;        // 2M x 4N
    const int m_w = wm * 32, n_w = wn * 32;
    const int g = lane >> 2, t = lane & 3;

    const int zb = blockIdx.z % nz;
    const int sp = blockIdx.z / nz;
    A  += zb * sA + sp * aSplit;
    BT += zb * sB + sp * bSplit;
    bias += zb * biasZ;
    const long cbase = zb * sC + sp * cSplit;

    const long m0 = (long)blockIdx.x * 64;
    const int  n0 = blockIdx.y * 128;

    const int niter = (K + 31) / 32;

    float acc[2][4][4];
#pragma unroll
    for (int a = 0; a < 2; a++)
#pragma unroll
        for (int b = 0; b < 4; b++)
#pragma unroll
            for (int c = 0; c < 4; c++) acc[a][b][c] = 0.f;

    // ---- persistent loader state (pointer-increment) ----
    const uint32_t* pA[2];
    uint32_t aDst[2];
    int aCC[2];
    bool aMok[2];
    int aStep;
    if constexpr (!TRANS_A) {
        aStep = 32;
#pragma unroll
        for (int p = 0; p < 2; p++) {
            const int ch = tid + p * 256;
            const int row = ch >> 3, c = ch & 7;
            const long gm = m0 + row;
            aMok[p] = (gm < M);
            aCC[p] = c * 4;
            pA[p] = A + (aMok[p] ? gm * (long)lda + c * 4 : 0);
            aDst[p] = as0 + row * 144 + c * 16;
        }
    } else {
        aStep = 32 * lda;
#pragma unroll
        for (int p = 0; p < 2; p++) {
            const int ch = tid + p * 256;
            const int kr = ch >> 4, m4 = ch & 15;
            const long gm = m0 + m4 * 4;
            aMok[p] = (gm < M);
            aCC[p] = kr;
            pA[p] = A + (aMok[p] ? (long)kr * lda + gm : 0);
            aDst[p] = as0 + kr * 272 + m4 * 16;
        }
    }
    const uint32_t* pB[4];
    uint32_t bDst[4];
    int bCC[4];
#pragma unroll
    for (int p = 0; p < 4; p++) {
        const int ch = tid + p * 256;
        const int r = ch >> 3, c = ch & 7;
        bCC[p] = c * 4;
        pB[p] = BT + (long)(n0 + r) * ldb + c * 4;
        bDst[p] = bs0 + r * 144 + c * 16;
    }

    auto issue = [&](int it, int stage) {
        const int k0 = it * 32;
        const uint32_t aOff = stage * AS_BYTES;
        const uint32_t bOff = stage * BS_BYTES;
#pragma unroll
        for (int p = 0; p < 2; p++) {
            const bool ok = aMok[p] && (k0 + aCC[p] < K);
            cpasync16(aDst[p] + aOff, ok ? pA[p] : A, ok ? 16u : 0u);
            pA[p] += aStep;
        }
#pragma unroll
        for (int p = 0; p < 4; p++) {
            const bool ok = (k0 + bCC[p] < K);
            cpasync16(bDst[p] + bOff, ok ? pB[p] : BT, ok ? 16u : 0u);
            pB[p] += 32;
        }
        CP_COMMIT();
    };

    auto compute = [&](int stage) {
        const uint32_t as = as0 + stage * AS_BYTES;
        const uint32_t bs = bs0 + stage * BS_BYTES;
#pragma unroll
        for (int ks = 0; ks < 4; ks++) {
            uint32_t a[2][4], b[4][2];
            if constexpr (!TRANS_A) {
#pragma unroll
                for (int mt = 0; mt < 2; mt++) {
                    const uint32_t addr = as +
                        (m_w + mt * 16 + (lane & 15)) * 144 +
                        ks * 32 + ((lane >> 4) << 4);
                    ldsm_x4(a[mt], addr);
                }
            } else {
                const uint32_t base = as + (ks * 8 + t) * 272 + (m_w + g) * 4;
#pragma unroll
                for (int mt = 0; mt < 2; mt++) {
                    const uint32_t ab = base + mt * 64;
                    a[mt][0] = lds32(ab);
                    a[mt][1] = lds32(ab + 32);
                    a[mt][2] = lds32(ab + 4 * 272);
                    a[mt][3] = lds32(ab + 4 * 272 + 32);
                }
            }
            if constexpr (A_CVT) {
#pragma unroll
                for (int mt = 0; mt < 2; mt++)
#pragma unroll
                    for (int q = 0; q < 4; q++)
                        a[mt][q] = f2tf32(__uint_as_float(a[mt][q]));
            }
#pragma unroll
            for (int np = 0; np < 2; np++) {
                uint32_t r4[4];
                const uint32_t addr = bs +
                    (n_w + np * 16 + ((lane >> 4) << 3) + (lane & 7)) * 144 +
                    ks * 32 + (((lane >> 3) & 1) << 4);
                ldsm_x4(r4, addr);
                b[np * 2][0] = r4[0];
                b[np * 2][1] = r4[1];
                b[np * 2 + 1][0] = r4[2];
                b[np * 2 + 1][1] = r4[3];
            }
#pragma unroll
            for (int mt = 0; mt < 2; mt++)
#pragma unroll
                for (int nt = 0; nt < 4; nt++)
                    mma_tf32(acc[mt][nt], a[mt], b[nt][0], b[nt][1]);
        }
    };

    // ---- 2-stage mainloop ----
    issue(0, 0);
    for (int it = 0; it < niter; it++) {
        if (it + 1 < niter) {
            issue(it + 1, (it + 1) & 1);
        } else {
            CP_COMMIT();   // tail-race fix
        }
        CP_WAIT1();
        __syncthreads();
        compute(it & 1);
        __syncthreads();
    }

    // ---------------- epilogue ----------------
    const int tg = t * 2;
#pragma unroll
    for (int mt = 0; mt < 2; mt++) {
#pragma unroll
        for (int h = 0; h < 2; h++) {
            const long r = m0 + m_w + mt * 16 + g + h * 8;
            if (r >= M) continue;
            float gt = 0.f;
            float g5[5];
            if (EPI == 3) gt = gate[r * (long)gld + zb];
            if (EPI == 4) {
                const float* gr = gate + r * 5;
#pragma unroll
                for (int q = 0; q < 5; q++) g5[q] = gr[q];
            }
#pragma unroll
            for (int nt = 0; nt < 4; nt++) {
                const int col = n_w + nt * 8 + tg;   // [0,128)
                float v0 = acc[mt][nt][h * 2 + 0];
                float v1 = acc[mt][nt][h * 2 + 1];
                if (EPI == 3) {
                    float2 bb = *(const float2*)(bias + n0 + col);
                    v0 = fmaxf(v0 + bb.x, 0.f) * gt;
                    v1 = fmaxf(v1 + bb.y, 0.f) * gt;
                } else if (EPI == 4) {
#pragma unroll
                    for (int q = 0; q < 5; q++) {
                        float2 bb = *(const float2*)(bias + q * 256 + n0 + col);
                        v0 += g5[q] * bb.x;
                        v1 += g5[q] * bb.y;
                    }
                }
                if constexpr (OUT_TF32) {
                    uint32_t* p = (uint32_t*)Cv + cbase + r * (long)ldc + n0 + col;
                    uint2 o;
                    o.x = f2tf32(v0);
                    o.y = f2tf32(v1);
                    *reinterpret_cast<uint2*>(p) = o;
                } else {
                    float* p = (float*)Cv + cbase + r * (long)ldc + n0 + col;
                    *reinterpret_cast<float2*>(p) = make_float2(v0, v1);
                }
            }
        }
    }
}

// ---------------------------------------------------------------------------
// in fp32 [z][R][C] -> out tf32: out[z*sOut + (c)*ldOut + r]   (C%32==0)
__global__ void trans_cvt_kernel(const float* __restrict__ src,
                                 uint32_t* __restrict__ dst,
                                 int R, int C, long sIn, long sOut, int ldOut)
{
    __shared__ float tbuf[32][33];
    const int r0 = blockIdx.x * 32, c0 = blockIdx.y * 32, z = blockIdx.z;
    const int tx = threadIdx.x, ty = threadIdx.y;
    const float* in = src + (long)z * sIn;
#pragma unroll
    for (int i = ty; i < 32; i += 8) {
        const int r = r0 + i;
        tbuf[i][tx] = (r < R) ? in[(long)r * C + c0 + tx] : 0.f;
    }
    __syncthreads();
    uint32_t* outp = dst + (long)z * sOut;
#pragma unroll
    for (int i = ty; i < 32; i += 8) {
        const int r = r0 + tx;
        if (r < R) outp[(long)(c0 + i) * ldOut + r] = f2tf32(tbuf[tx][i]);
    }
}

// out[b,n,0:256] = sum_s part[s][b][n][:]; out[b,n,256:512] = ori[b,n,:]
__global__ void finalize_kernel(const float* __restrict__ part,
                                const float* __restrict__ ori,
                                float* __restrict__ out, int total4)
{
    const int idx = blockIdx.x * blockDim.x + threadIdx.x;
    if (idx >= total4) return;
    const int d4 = idx & 63;
    const int bn = idx >> 6;
    const long stride4 = 4L * 2000 * 64;
    float4 s = ((const float4*)part)[idx];
#pragma unroll
    for (int sp = 1; sp < 4; sp++) {
        float4 v = ((const float4*)part)[idx + sp * stride4];
        s.x += v.x; s.y += v.y; s.z += v.z; s.w += v.w;
    }
    ((float4*)out)[(long)bn * 128 + d4] = s;
    float4 o = ((const float4*)ori)[idx];
    ((float4*)out)[(long)bn * 128 + 64 + d4] = o;
}

// ---------------------------------------------------------------------------
extern "C" void kernel_launch(void* const* d_in, const int* in_sizes, int n_in,
                              void* d_out, int out_size)
{
    const float* ed  = (const float*)d_in[0];   // [4,8000,5]
    const float* H   = (const float*)d_in[1];   // [4,8000,2000]
    const float* ori = (const float*)d_in[2];   // [4,2000,256]
    const float* W1  = (const float*)d_in[3];   // [5,256,128]
    const float* b1  = (const float*)d_in[4];   // [5,128]
    const float* W2  = (const float*)d_in[5];   // [5,128,256]
    const float* b2  = (const float*)d_in[6];   // [5,256]
    float* out = (float*)d_out;                 // [4,2000,512]

    uint32_t *oriT, *W1T, *W2cat, *edges, *htcat, *efT;
    float *ef, *part;
    cudaGetSymbolAddress((void**)&oriT, g_oriT);
    cudaGetSymbolAddress((void**)&W1T, g_W1T);
    cudaGetSymbolAddress((void**)&W2cat, g_W2cat);
    cudaGetSymbolAddress((void**)&edges, g_edges);
    cudaGetSymbolAddress((void**)&htcat, g_htcat);
    cudaGetSymbolAddress((void**)&ef, g_ef);
    cudaGetSymbolAddress((void**)&efT, g_efT);
    cudaGetSymbolAddress((void**)&part, g_part);

    const int SM_NT = 2 * (64 * 144 + 128 * 144);   // 55296
    const int SM_T  = 2 * (32 * 272 + 128 * 144);   // 54272
    cudaFuncSetAttribute(gemm_tf32<0, false, true, true>,
                         cudaFuncAttributeMaxDynamicSharedMemorySize, SM_NT);
    cudaFuncSetAttribute(gemm_tf32<3, false, false, true>,
                         cudaFuncAttributeMaxDynamicSharedMemorySize, SM_NT);
    cudaFuncSetAttribute(gemm_tf32<4, false, false, false>,
                         cudaFuncAttributeMaxDynamicSharedMemorySize, SM_NT);
    cudaFuncSetAttribute(gemm_tf32<0, true, true, false>,
                         cudaFuncAttributeMaxDynamicSharedMemorySize, SM_T);

    // 0) transpose+convert B operands
    trans_cvt_kernel<<<dim3(63, 8, 4), dim3(32, 8)>>>(
        ori, oriT, 2000, 256, 2000L * 256, 2000L * 256, 2000);
    trans_cvt_kernel<<<dim3(8, 4, 5), dim3(32, 8)>>>(
        W1, W1T, 256, 128, 256L * 128, 256L * 128, 256);
    // W2 [t][128 h][256 d] -> W2cat[d][t*128+h]  (ldOut=640, z offset = t*128)
    trans_cvt_kernel<<<dim3(4, 8, 5), dim3(32, 8)>>>(
        W2, W2cat, 128, 256, 128L * 256, 128, 640);

    // 1) edges = H @ ori   (A = H fp32 + in-loop cvt; B = oriT; tf32 out)
    gemm_tf32<0, false, true, true><<<dim3(125, 2, 4), 256, SM_NT>>>(
        (const uint32_t*)H, oriT, edges, 8000, 256, 2000,
        8000L * 2000, 256L * 2000, 8000L * 256, 0, 0, 0, 4,
        2000, 2000, 256, nullptr, 0, nullptr, 0);

    // 2a) MLP1 (z = t): htcat[:, t*128:(t+1)*128] = relu(edges@W1_t+b1_t)*gate_t
    gemm_tf32<3, false, false, true><<<dim3(500, 1, 5), 256, SM_NT>>>(
        edges, W1T, htcat, 32000, 128, 256,
        0, 128L * 256, 128 /* z col offset */, 0, 0, 0, 5,
        256, 256, 640, b1, 128, ed, 5);

    // 2b) fused MLP2: ef = htcat @ W2cat + sum_t gate_t*b2_t   (K=640, 1 launch)
    gemm_tf32<4, false, false, false><<<dim3(500, 2, 1), 256, SM_NT>>>(
        htcat, W2cat, ef, 32000, 256, 640,
        0, 0, 0, 0, 0, 0, 1,
        640, 640, 256, b2, 0, ed, 5);

    // 3) efT = transpose+convert(ef) per batch: [8000,256] -> [256,8000]
    trans_cvt_kernel<<<dim3(250, 8, 4), dim3(32, 8)>>>(
        ef, efT, 8000, 256, 8000L * 256, 256L * 8000, 8000);

    // 4) part[s] = H[ks]^T @ ef[ks]  (split-K x4; A = H fp32 TRANS + cvt)
    gemm_tf32<0, true, true, false><<<dim3(32, 2, 16), 256, SM_T>>>(
        (const uint32_t*)H, efT, part, 2000, 256, 2000,
        8000L * 2000, 256L * 8000, 2000L * 256,
        2000L * 2000, 2000, 4L * 2000 * 256, 4,
        2000, 8000, 256, nullptr, 0, nullptr, 0);

    // 5) out = [reduce(part), ori]
    finalize_kernel<<<(4 * 2000 * 64 + 255) / 256, 256>>>(
        part, ori, out, 4 * 2000 * 64);
}

// round 16
// speedup vs baseline: 1.0963x; 1.0963x over previous
#include <cuda_runtime.h>
#include <cstdint>

// ---------------------------------------------------------------------------
// edge_aggregation (B=4, E=8000, N=2000, D=256, HID=128, T=5)
// tf32 mma.sync.m16n8k8 + cp.async 2-stage pipeline + ldmatrix fragments,
// 3 CTAs/SM (round-15's 4-CTA cap spilled; reverted).
// Round 16: grid axes swapped globally (x = n-tile, y = m-tile) so CTAs
// sharing the same A rows (H slice) are consecutive bids -> co-resident ->
// second CTA's A loads hit L2 instead of DRAM.
//   edges = H @ ori                      GEMM1  M=8000 N=256 K=2000  x4
//   htcat[:,t*128:+128] = relu(edges@W1_t+b1_t)*gate_t    MLP1 (1 launch, z=t)
//   ef    = htcat @ W2cat + sum_t gate_t*b2_t             MLP2 (1 launch, K=640)
//   out[:, :256] = H^T @ ef              GEMM3  M=2000 N=256 K=8000  split-K x4
//   out[:, 256:] = ori
// ---------------------------------------------------------------------------

__device__ uint32_t g_oriT[4 * 256 * 2000];      // [b][d][n] tf32
__device__ uint32_t g_W1T[5 * 128 * 256];        // [t][h][d] tf32
__device__ uint32_t g_W2cat[256 * 640];          // [d][t*128+h] tf32
__device__ uint32_t g_edges[32000 * 256];        // tf32 (GEMM1 out)
__device__ uint32_t g_htcat[32000L * 640];       // tf32 (MLP1 out, gated, concat-K)
__device__ float    g_ef[32000 * 256];           // fp32 (MLP2 out)
__device__ uint32_t g_efT[4 * 256 * 8000];       // [b][d][e] tf32
__device__ float    g_part[4L * 4 * 2000 * 256]; // split-K partials

// ---------------- PTX helpers ----------------
__device__ __forceinline__ uint32_t smem_u32(const void* p) {
    uint32_t a;
    asm("{ .reg .u64 t; cvta.to.shared.u64 t, %1; cvt.u32.u64 %0, t; }"
        : "=r"(a) : "l"(p));
    return a;
}
__device__ __forceinline__ void cpasync16(uint32_t dst, const void* src, uint32_t sz) {
    asm volatile("cp.async.cg.shared.global [%0], [%1], 16, %2;"
                 :: "r"(dst), "l"(src), "r"(sz) : "memory");
}
#define CP_COMMIT() asm volatile("cp.async.commit_group;" ::: "memory")
#define CP_WAIT1()  asm volatile("cp.async.wait_group 1;" ::: "memory")

__device__ __forceinline__ uint32_t lds32(uint32_t a) {
    uint32_t v;
    asm volatile("ld.shared.b32 %0, [%1];" : "=r"(v) : "r"(a));
    return v;
}
__device__ __forceinline__ void ldsm_x4(uint32_t (&r)[4], uint32_t a) {
    asm volatile("ldmatrix.sync.aligned.m8n8.x4.shared.b16 {%0,%1,%2,%3}, [%4];"
                 : "=r"(r[0]), "=r"(r[1]), "=r"(r[2]), "=r"(r[3]) : "r"(a));
}
__device__ __forceinline__ uint32_t f2tf32(float x) {
    uint32_t r;
    asm("cvt.rna.tf32.f32 %0, %1;" : "=r"(r) : "f"(x));
    return r;
}
__device__ __forceinline__ void mma_tf32(float (&c)[4], const uint32_t (&a)[4],
                                         uint32_t b0, uint32_t b1) {
    asm volatile(
        "mma.sync.aligned.m16n8k8.row.col.f32.tf32.tf32.f32 "
        "{%0,%1,%2,%3}, {%4,%5,%6,%7}, {%8,%9}, {%0,%1,%2,%3};"
        : "+f"(c[0]), "+f"(c[1]), "+f"(c[2]), "+f"(c[3])
        : "r"(a[0]), "r"(a[1]), "r"(a[2]), "r"(a[3]), "r"(b0), "r"(b1));
}

// ---------------------------------------------------------------------------
// Tile 64x128, K-chunk 32, 256 threads (8 warps: 2M x 4N, 32x32 per warp).
// 2-stage pipeline, 55KB smem/CTA, __launch_bounds__(256,3) -> 3 CTAs/SM.
// GRID: x = n-tile index, y = m-tile index (consecutive bids share A rows).
// Tail iterations commit an empty cp.async group (round-11 race fix).
// EPI 0: C=acc
// EPI 3: C=relu(acc+bias[z])*gate[r*gld+zb]         (MLP1, OUT_TF32)
// EPI 4: C=acc + sum_t gate[r*5+t]*bias[t*256+col]  (fused MLP2, fp32 out)
// ---------------------------------------------------------------------------
template <int EPI, bool TRANS_A, bool A_CVT, bool OUT_TF32>
__global__ __launch_bounds__(256, 3)
void gemm_tf32(const uint32_t* __restrict__ A, const uint32_t* __restrict__ BT,
               void* __restrict__ Cv, int M, int N, int K,
               long sA, long sB, long sC,
               long aSplit, long bSplit, long cSplit, int nz,
               int lda, int ldb, int ldc,
               const float* __restrict__ bias, long biasZ,
               const float* __restrict__ gate, int gld)
{
    constexpr int AS_BYTES = TRANS_A ? 32 * 272 : 64 * 144;
    constexpr int BS_BYTES = 128 * 144;

    extern __shared__ __align__(16) char dyn[];
    const uint32_t as0 = smem_u32(dyn);
    const uint32_t bs0 = as0 + 2 * AS_BYTES;

    const int tid = threadIdx.x;
    const int warp = tid >> 5, lane = tid & 31;
    const int wm = warp & 1, wn = warp >> 1;        // 2M x 4N
    const int m_w = wm * 32, n_w = wn * 32;
    const int g = lane >> 2, t = lane & 3;

    const int zb = blockIdx.z % nz;
    const int sp = blockIdx.z / nz;
    A  += zb * sA + sp * aSplit;
    BT += zb * sB + sp * bSplit;
    bias += zb * biasZ;
    const long cbase = zb * sC + sp * cSplit;

    // axis swap: y = m-tile (A slice shared among consecutive x), x = n-tile
    const long m0 = (long)blockIdx.y * 64;
    const int  n0 = blockIdx.x * 128;

    const int niter = (K + 31) / 32;

    float acc[2][4][4];
#pragma unroll
    for (int a = 0; a < 2; a++)
#pragma unroll
        for (int b = 0; b < 4; b++)
#pragma unroll
            for (int c = 0; c < 4; c++) acc[a][b][c] = 0.f;

    // ---- persistent loader state (pointer-increment) ----
    const uint32_t* pA[2];
    uint32_t aDst[2];
    int aCC[2];
    bool aMok[2];
    int aStep;
    if constexpr (!TRANS_A) {
        aStep = 32;
#pragma unroll
        for (int p = 0; p < 2; p++) {
            const int ch = tid + p * 256;
            const int row = ch >> 3, c = ch & 7;
            const long gm = m0 + row;
            aMok[p] = (gm < M);
            aCC[p] = c * 4;
            pA[p] = A + (aMok[p] ? gm * (long)lda + c * 4 : 0);
            aDst[p] = as0 + row * 144 + c * 16;
        }
    } else {
        aStep = 32 * lda;
#pragma unroll
        for (int p = 0; p < 2; p++) {
            const int ch = tid + p * 256;
            const int kr = ch >> 4, m4 = ch & 15;
            const long gm = m0 + m4 * 4;
            aMok[p] = (gm < M);
            aCC[p] = kr;
            pA[p] = A + (aMok[p] ? (long)kr * lda + gm : 0);
            aDst[p] = as0 + kr * 272 + m4 * 16;
        }
    }
    const uint32_t* pB[4];
    uint32_t bDst[4];
    int bCC[4];
#pragma unroll
    for (int p = 0; p < 4; p++) {
        const int ch = tid + p * 256;
        const int r = ch >> 3, c = ch & 7;
        bCC[p] = c * 4;
        pB[p] = BT + (long)(n0 + r) * ldb + c * 4;
        bDst[p] = bs0 + r * 144 + c * 16;
    }

    auto issue = [&](int it, int stage) {
        const int k0 = it * 32;
        const uint32_t aOff = stage * AS_BYTES;
        const uint32_t bOff = stage * BS_BYTES;
#pragma unroll
        for (int p = 0; p < 2; p++) {
            const bool ok = aMok[p] && (k0 + aCC[p] < K);
            cpasync16(aDst[p] + aOff, ok ? pA[p] : A, ok ? 16u : 0u);
            pA[p] += aStep;
        }
#pragma unroll
        for (int p = 0; p < 4; p++) {
            const bool ok = (k0 + bCC[p] < K);
            cpasync16(bDst[p] + bOff, ok ? pB[p] : BT, ok ? 16u : 0u);
            pB[p] += 32;
        }
        CP_COMMIT();
    };

    auto compute = [&](int stage) {
        const uint32_t as = as0 + stage * AS_BYTES;
        const uint32_t bs = bs0 + stage * BS_BYTES;
#pragma unroll
        for (int ks = 0; ks < 4; ks++) {
            uint32_t a[2][4], b[4][2];
            if constexpr (!TRANS_A) {
#pragma unroll
                for (int mt = 0; mt < 2; mt++) {
                    const uint32_t addr = as +
                        (m_w + mt * 16 + (lane & 15)) * 144 +
                        ks * 32 + ((lane >> 4) << 4);
                    ldsm_x4(a[mt], addr);
                }
            } else {
                const uint32_t base = as + (ks * 8 + t) * 272 + (m_w + g) * 4;
#pragma unroll
                for (int mt = 0; mt < 2; mt++) {
                    const uint32_t ab = base + mt * 64;
                    a[mt][0] = lds32(ab);
                    a[mt][1] = lds32(ab + 32);
                    a[mt][2] = lds32(ab + 4 * 272);
                    a[mt][3] = lds32(ab + 4 * 272 + 32);
                }
            }
            if constexpr (A_CVT) {
#pragma unroll
                for (int mt = 0; mt < 2; mt++)
#pragma unroll
                    for (int q = 0; q < 4; q++)
                        a[mt][q] = f2tf32(__uint_as_float(a[mt][q]));
            }
#pragma unroll
            for (int np = 0; np < 2; np++) {
                uint32_t r4[4];
                const uint32_t addr = bs +
                    (n_w + np * 16 + ((lane >> 4) << 3) + (lane & 7)) * 144 +
                    ks * 32 + (((lane >> 3) & 1) << 4);
                ldsm_x4(r4, addr);
                b[np * 2][0] = r4[0];
                b[np * 2][1] = r4[1];
                b[np * 2 + 1][0] = r4[2];
                b[np * 2 + 1][1] = r4[3];
            }
#pragma unroll
            for (int mt = 0; mt < 2; mt++)
#pragma unroll
                for (int nt = 0; nt < 4; nt++)
                    mma_tf32(acc[mt][nt], a[mt], b[nt][0], b[nt][1]);
        }
    };

    // ---- 2-stage mainloop ----
    issue(0, 0);
    for (int it = 0; it < niter; it++) {
        if (it + 1 < niter) {
            issue(it + 1, (it + 1) & 1);
        } else {
            CP_COMMIT();   // tail-race fix
        }
        CP_WAIT1();
        __syncthreads();
        compute(it & 1);
        __syncthreads();
    }

    // ---------------- epilogue ----------------
    const int tg = t * 2;
#pragma unroll
    for (int mt = 0; mt < 2; mt++) {
#pragma unroll
        for (int h = 0; h < 2; h++) {
            const long r = m0 + m_w + mt * 16 + g + h * 8;
            if (r >= M) continue;
            float gt = 0.f;
            float g5[5];
            if (EPI == 3) gt = gate[r * (long)gld + zb];
            if (EPI == 4) {
                const float* gr = gate + r * 5;
#pragma unroll
                for (int q = 0; q < 5; q++) g5[q] = gr[q];
            }
#pragma unroll
            for (int nt = 0; nt < 4; nt++) {
                const int col = n_w + nt * 8 + tg;   // [0,128)
                float v0 = acc[mt][nt][h * 2 + 0];
                float v1 = acc[mt][nt][h * 2 + 1];
                if (EPI == 3) {
                    float2 bb = *(const float2*)(bias + n0 + col);
                    v0 = fmaxf(v0 + bb.x, 0.f) * gt;
                    v1 = fmaxf(v1 + bb.y, 0.f) * gt;
                } else if (EPI == 4) {
#pragma unroll
                    for (int q = 0; q < 5; q++) {
                        float2 bb = *(const float2*)(bias + q * 256 + n0 + col);
                        v0 += g5[q] * bb.x;
                        v1 += g5[q] * bb.y;
                    }
                }
                if constexpr (OUT_TF32) {
                    uint32_t* p = (uint32_t*)Cv + cbase + r * (long)ldc + n0 + col;
                    uint2 o;
                    o.x = f2tf32(v0);
                    o.y = f2tf32(v1);
                    *reinterpret_cast<uint2*>(p) = o;
                } else {
                    float* p = (float*)Cv + cbase + r * (long)ldc + n0 + col;
                    *reinterpret_cast<float2*>(p) = make_float2(v0, v1);
                }
            }
        }
    }
}

// ---------------------------------------------------------------------------
// in fp32 [z][R][C] -> out tf32: out[z*sOut + (c)*ldOut + r]   (C%32==0)
__global__ void trans_cvt_kernel(const float* __restrict__ src,
                                 uint32_t* __restrict__ dst,
                                 int R, int C, long sIn, long sOut, int ldOut)
{
    __shared__ float tbuf[32][33];
    const int r0 = blockIdx.x * 32, c0 = blockIdx.y * 32, z = blockIdx.z;
    const int tx = threadIdx.x, ty = threadIdx.y;
    const float* in = src + (long)z * sIn;
#pragma unroll
    for (int i = ty; i < 32; i += 8) {
        const int r = r0 + i;
        tbuf[i][tx] = (r < R) ? in[(long)r * C + c0 + tx] : 0.f;
    }
    __syncthreads();
    uint32_t* outp = dst + (long)z * sOut;
#pragma unroll
    for (int i = ty; i < 32; i += 8) {
        const int r = r0 + tx;
        if (r < R) outp[(long)(c0 + i) * ldOut + r] = f2tf32(tbuf[tx][i]);
    }
}

// out[b,n,0:256] = sum_s part[s][b][n][:]; out[b,n,256:512] = ori[b,n,:]
__global__ void finalize_kernel(const float* __restrict__ part,
                                const float* __restrict__ ori,
                                float* __restrict__ out, int total4)
{
    const int idx = blockIdx.x * blockDim.x + threadIdx.x;
    if (idx >= total4) return;
    const int d4 = idx & 63;
    const int bn = idx >> 6;
    const long stride4 = 4L * 2000 * 64;
    float4 s = ((const float4*)part)[idx];
#pragma unroll
    for (int sp = 1; sp < 4; sp++) {
        float4 v = ((const float4*)part)[idx + sp * stride4];
        s.x += v.x; s.y += v.y; s.z += v.z; s.w += v.w;
    }
    ((float4*)out)[(long)bn * 128 + d4] = s;
    float4 o = ((const float4*)ori)[idx];
    ((float4*)out)[(long)bn * 128 + 64 + d4] = o;
}

// ---------------------------------------------------------------------------
extern "C" void kernel_launch(void* const* d_in, const int* in_sizes, int n_in,
                              void* d_out, int out_size)
{
    const float* ed  = (const float*)d_in[0];   // [4,8000,5]
    const float* H   = (const float*)d_in[1];   // [4,8000,2000]
    const float* ori = (const float*)d_in[2];   // [4,2000,256]
    const float* W1  = (const float*)d_in[3];   // [5,256,128]
    const float* b1  = (const float*)d_in[4];   // [5,128]
    const float* W2  = (const float*)d_in[5];   // [5,128,256]
    const float* b2  = (const float*)d_in[6];   // [5,256]
    float* out = (float*)d_out;                 // [4,2000,512]

    uint32_t *oriT, *W1T, *W2cat, *edges, *htcat, *efT;
    float *ef, *part;
    cudaGetSymbolAddress((void**)&oriT, g_oriT);
    cudaGetSymbolAddress((void**)&W1T, g_W1T);
    cudaGetSymbolAddress((void**)&W2cat, g_W2cat);
    cudaGetSymbolAddress((void**)&edges, g_edges);
    cudaGetSymbolAddress((void**)&htcat, g_htcat);
    cudaGetSymbolAddress((void**)&ef, g_ef);
    cudaGetSymbolAddress((void**)&efT, g_efT);
    cudaGetSymbolAddress((void**)&part, g_part);

    const int SM_NT = 2 * (64 * 144 + 128 * 144);   // 55296
    const int SM_T  = 2 * (32 * 272 + 128 * 144);   // 54272
    cudaFuncSetAttribute(gemm_tf32<0, false, true, true>,
                         cudaFuncAttributeMaxDynamicSharedMemorySize, SM_NT);
    cudaFuncSetAttribute(gemm_tf32<3, false, false, true>,
                         cudaFuncAttributeMaxDynamicSharedMemorySize, SM_NT);
    cudaFuncSetAttribute(gemm_tf32<4, false, false, false>,
                         cudaFuncAttributeMaxDynamicSharedMemorySize, SM_NT);
    cudaFuncSetAttribute(gemm_tf32<0, true, true, false>,
                         cudaFuncAttributeMaxDynamicSharedMemorySize, SM_T);

    // 0) transpose+convert B operands
    trans_cvt_kernel<<<dim3(63, 8, 4), dim3(32, 8)>>>(
        ori, oriT, 2000, 256, 2000L * 256, 2000L * 256, 2000);
    trans_cvt_kernel<<<dim3(8, 4, 5), dim3(32, 8)>>>(
        W1, W1T, 256, 128, 256L * 128, 256L * 128, 256);
    // W2 [t][128 h][256 d] -> W2cat[d][t*128+h]  (ldOut=640, z offset = t*128)
    trans_cvt_kernel<<<dim3(4, 8, 5), dim3(32, 8)>>>(
        W2, W2cat, 128, 256, 128L * 256, 128, 640);

    // 1) edges = H @ ori   (grid: x=n-tiles(2), y=m-tiles(125), z=batch)
    gemm_tf32<0, false, true, true><<<dim3(2, 125, 4), 256, SM_NT>>>(
        (const uint32_t*)H, oriT, edges, 8000, 256, 2000,
        8000L * 2000, 256L * 2000, 8000L * 256, 0, 0, 0, 4,
        2000, 2000, 256, nullptr, 0, nullptr, 0);

    // 2a) MLP1 (z = t): htcat[:, t*128:(t+1)*128] = relu(edges@W1_t+b1_t)*gate_t
    gemm_tf32<3, false, false, true><<<dim3(1, 500, 5), 256, SM_NT>>>(
        edges, W1T, htcat, 32000, 128, 256,
        0, 128L * 256, 128 /* z col offset */, 0, 0, 0, 5,
        256, 256, 640, b1, 128, ed, 5);

    // 2b) fused MLP2: ef = htcat @ W2cat + sum_t gate_t*b2_t   (K=640, 1 launch)
    gemm_tf32<4, false, false, false><<<dim3(2, 500, 1), 256, SM_NT>>>(
        htcat, W2cat, ef, 32000, 256, 640,
        0, 0, 0, 0, 0, 0, 1,
        640, 640, 256, b2, 0, ed, 5);

    // 3) efT = transpose+convert(ef) per batch: [8000,256] -> [256,8000]
    trans_cvt_kernel<<<dim3(250, 8, 4), dim3(32, 8)>>>(
        ef, efT, 8000, 256, 8000L * 256, 256L * 8000, 8000);

    // 4) part[s] = H[ks]^T @ ef[ks]  (split-K x4; grid x=n(2), y=m(32))
    gemm_tf32<0, true, true, false><<<dim3(2, 32, 16), 256, SM_T>>>(
        (const uint32_t*)H, efT, part, 2000, 256, 2000,
        8000L * 2000, 256L * 8000, 2000L * 256,
        2000L * 2000, 2000, 4L * 2000 * 256, 4,
        2000, 8000, 256, nullptr, 0, nullptr, 0);

    // 5) out = [reduce(part), ori]
    finalize_kernel<<<(4 * 2000 * 64 + 255) / 256, 256>>>(
        part, ori, out, 4 * 2000 * 64);
}

// round 17
// speedup vs baseline: 1.2139x; 1.1073x over previous
#include <cuda_runtime.h>
#include <cstdint>

// ---------------------------------------------------------------------------
// edge_aggregation (B=4, E=8000, N=2000, D=256, HID=128, T=5)
// tf32 mma.sync.m16n8k8 + cp.async + ldmatrix fragments, 3 CTAs/SM.
// Round 17: 3-stage pipeline with ONE __syncthreads per K-chunk (vs 2 in the
// 2-stage loop), kept at 3 CTAs/SM by removing smem padding with an
// ldmatrix-phase-aware XOR swizzle: granule g of row r lives at g^(r&7).
// Grid ordering reverted to round-14 (x = m-tile fastest).
//   edges = H @ ori                      GEMM1  M=8000 N=256 K=2000  x4
//   htcat[:,t*128:+128] = relu(edges@W1_t+b1_t)*gate_t    MLP1 (1 launch, z=t)
//   ef    = htcat @ W2cat + sum_t gate_t*b2_t             MLP2 (1 launch, K=640)
//   out[:, :256] = H^T @ ef              GEMM3  M=2000 N=256 K=8000  split-K x4
//   out[:, 256:] = ori
// ---------------------------------------------------------------------------

__device__ uint32_t g_oriT[4 * 256 * 2000];      // [b][d][n] tf32
__device__ uint32_t g_W1T[5 * 128 * 256];        // [t][h][d] tf32
__device__ uint32_t g_W2cat[256 * 640];          // [d][t*128+h] tf32
__device__ uint32_t g_edges[32000 * 256];        // tf32 (GEMM1 out)
__device__ uint32_t g_htcat[32000L * 640];       // tf32 (MLP1 out, gated, concat-K)
__device__ float    g_ef[32000 * 256];           // fp32 (MLP2 out)
__device__ uint32_t g_efT[4 * 256 * 8000];       // [b][d][e] tf32
__device__ float    g_part[4L * 4 * 2000 * 256]; // split-K partials

// ---------------- PTX helpers ----------------
__device__ __forceinline__ uint32_t smem_u32(const void* p) {
    uint32_t a;
    asm("{ .reg .u64 t; cvta.to.shared.u64 t, %1; cvt.u32.u64 %0, t; }"
        : "=r"(a) : "l"(p));
    return a;
}
__device__ __forceinline__ void cpasync16(uint32_t dst, const void* src, uint32_t sz) {
    asm volatile("cp.async.cg.shared.global [%0], [%1], 16, %2;"
                 :: "r"(dst), "l"(src), "r"(sz) : "memory");
}
#define CP_COMMIT() asm volatile("cp.async.commit_group;" ::: "memory")
#define CP_WAIT1()  asm volatile("cp.async.wait_group 1;" ::: "memory")

__device__ __forceinline__ uint32_t lds32(uint32_t a) {
    uint32_t v;
    asm volatile("ld.shared.b32 %0, [%1];" : "=r"(v) : "r"(a));
    return v;
}
__device__ __forceinline__ void ldsm_x4(uint32_t (&r)[4], uint32_t a) {
    asm volatile("ldmatrix.sync.aligned.m8n8.x4.shared.b16 {%0,%1,%2,%3}, [%4];"
                 : "=r"(r[0]), "=r"(r[1]), "=r"(r[2]), "=r"(r[3]) : "r"(a));
}
__device__ __forceinline__ uint32_t f2tf32(float x) {
    uint32_t r;
    asm("cvt.rna.tf32.f32 %0, %1;" : "=r"(r) : "f"(x));
    return r;
}
__device__ __forceinline__ void mma_tf32(float (&c)[4], const uint32_t (&a)[4],
                                         uint32_t b0, uint32_t b1) {
    asm volatile(
        "mma.sync.aligned.m16n8k8.row.col.f32.tf32.tf32.f32 "
        "{%0,%1,%2,%3}, {%4,%5,%6,%7}, {%8,%9}, {%0,%1,%2,%3};"
        : "+f"(c[0]), "+f"(c[1]), "+f"(c[2]), "+f"(c[3])
        : "r"(a[0]), "r"(a[1]), "r"(a[2]), "r"(a[3]), "r"(b0), "r"(b1));
}

// ---------------------------------------------------------------------------
// Tile 64x128, K-chunk 32, 256 threads (8 warps: 2M x 4N, 32x32 per warp).
// 3-STAGE pipeline, single __syncthreads per chunk. Unpadded XOR-swizzled
// smem: A non-trans [64 rows][128B], B [128 rows][128B]; 16B granule g of
// row r stored at granule g^(r&7) (conflict-free per ldsm 8-lane phase and
// for cp.async row writes). A trans keeps the padded 272B-row layout.
// Smem: NT 3*(8192+16384)=73728B; T 3*(8704+16384)=75264B -> 3 CTAs/SM.
// Tail iterations commit an empty cp.async group (round-11 race fix).
// EPI 0: C=acc
// EPI 3: C=relu(acc+bias[z])*gate[r*gld+zb]         (MLP1, OUT_TF32)
// EPI 4: C=acc + sum_t gate[r*5+t]*bias[t*256+col]  (fused MLP2, fp32 out)
// ---------------------------------------------------------------------------
template <int EPI, bool TRANS_A, bool A_CVT, bool OUT_TF32>
__global__ __launch_bounds__(256, 3)
void gemm_tf32(const uint32_t* __restrict__ A, const uint32_t* __restrict__ BT,
               void* __restrict__ Cv, int M, int N, int K,
               long sA, long sB, long sC,
               long aSplit, long bSplit, long cSplit, int nz,
               int lda, int ldb, int ldc,
               const float* __restrict__ bias, long biasZ,
               const float* __restrict__ gate, int gld)
{
    constexpr int AS_BYTES = TRANS_A ? 32 * 272 : 64 * 128;
    constexpr int BS_BYTES = 128 * 128;

    extern __shared__ __align__(16) char dyn[];
    const uint32_t as0 = smem_u32(dyn);
    const uint32_t bs0 = as0 + 3 * AS_BYTES;

    const int tid = threadIdx.x;
    const int warp = tid >> 5, lane = tid & 31;
    const int wm = warp & 1, wn = warp >> 1;        // 2M x 4N
    const int m_w = wm * 32, n_w = wn * 32;
    const int g = lane >> 2, t = lane & 3;

    const int zb = blockIdx.z % nz;
    const int sp = blockIdx.z / nz;
    A  += zb * sA + sp * aSplit;
    BT += zb * sB + sp * bSplit;
    bias += zb * biasZ;
    const long cbase = zb * sC + sp * cSplit;

    const long m0 = (long)blockIdx.x * 64;          // x = m-tile (round-14 order)
    const int  n0 = blockIdx.y * 128;

    const int niter = (K + 31) / 32;

    float acc[2][4][4];
#pragma unroll
    for (int a = 0; a < 2; a++)
#pragma unroll
        for (int b = 0; b < 4; b++)
#pragma unroll
            for (int c = 0; c < 4; c++) acc[a][b][c] = 0.f;

    // ---- persistent loader state (pointer-increment; swizzled dst) ----
    const uint32_t* pA[2];
    uint32_t aDst[2];
    int aCC[2];
    bool aMok[2];
    int aStep;
    if constexpr (!TRANS_A) {
        aStep = 32;
#pragma unroll
        for (int p = 0; p < 2; p++) {
            const int ch = tid + p * 256;
            const int row = ch >> 3, c = ch & 7;
            const long gm = m0 + row;
            aMok[p] = (gm < M);
            aCC[p] = c * 4;
            pA[p] = A + (aMok[p] ? gm * (long)lda + c * 4 : 0);
            aDst[p] = as0 + row * 128 + ((c ^ (row & 7)) << 4);
        }
    } else {
        aStep = 32 * lda;
#pragma unroll
        for (int p = 0; p < 2; p++) {
            const int ch = tid + p * 256;
            const int kr = ch >> 4, m4 = ch & 15;
            const long gm = m0 + m4 * 4;
            aMok[p] = (gm < M);
            aCC[p] = kr;
            pA[p] = A + (aMok[p] ? (long)kr * lda + gm : 0);
            aDst[p] = as0 + kr * 272 + m4 * 16;
        }
    }
    const uint32_t* pB[4];
    uint32_t bDst[4];
    int bCC[4];
#pragma unroll
    for (int p = 0; p < 4; p++) {
        const int ch = tid + p * 256;
        const int r = ch >> 3, c = ch & 7;
        bCC[p] = c * 4;
        pB[p] = BT + (long)(n0 + r) * ldb + c * 4;
        bDst[p] = bs0 + r * 128 + ((c ^ (r & 7)) << 4);
    }

    auto issue = [&](int it, int stage) {
        const int k0 = it * 32;
        const uint32_t aOff = stage * AS_BYTES;
        const uint32_t bOff = stage * BS_BYTES;
#pragma unroll
        for (int p = 0; p < 2; p++) {
            const bool ok = aMok[p] && (k0 + aCC[p] < K);
            cpasync16(aDst[p] + aOff, ok ? pA[p] : A, ok ? 16u : 0u);
            pA[p] += aStep;
        }
#pragma unroll
        for (int p = 0; p < 4; p++) {
            const bool ok = (k0 + bCC[p] < K);
            cpasync16(bDst[p] + bOff, ok ? pB[p] : BT, ok ? 16u : 0u);
            pB[p] += 32;
        }
        CP_COMMIT();
    };

    auto compute = [&](int stage) {
        const uint32_t as = as0 + stage * AS_BYTES;
        const uint32_t bs = bs0 + stage * BS_BYTES;
#pragma unroll
        for (int ks = 0; ks < 4; ks++) {
            uint32_t a[2][4], b[4][2];
            if constexpr (!TRANS_A) {
#pragma unroll
                for (int mt = 0; mt < 2; mt++) {
                    const int m = m_w + mt * 16 + (lane & 15);
                    const uint32_t addr = as + m * 128 +
                        (((ks * 2 + (lane >> 4)) ^ (m & 7)) << 4);
                    ldsm_x4(a[mt], addr);
                }
            } else {
                const uint32_t base = as + (ks * 8 + t) * 272 + (m_w + g) * 4;
#pragma unroll
                for (int mt = 0; mt < 2; mt++) {
                    const uint32_t ab = base + mt * 64;
                    a[mt][0] = lds32(ab);
                    a[mt][1] = lds32(ab + 32);
                    a[mt][2] = lds32(ab + 4 * 272);
                    a[mt][3] = lds32(ab + 4 * 272 + 32);
                }
            }
            if constexpr (A_CVT) {
#pragma unroll
                for (int mt = 0; mt < 2; mt++)
#pragma unroll
                    for (int q = 0; q < 4; q++)
                        a[mt][q] = f2tf32(__uint_as_float(a[mt][q]));
            }
#pragma unroll
            for (int np = 0; np < 2; np++) {
                uint32_t r4[4];
                const int n = n_w + np * 16 + ((lane >> 4) << 3) + (lane & 7);
                const uint32_t addr = bs + n * 128 +
                    (((ks * 2 + ((lane >> 3) & 1)) ^ (n & 7)) << 4);
                ldsm_x4(r4, addr);
                b[np * 2][0] = r4[0];
                b[np * 2][1] = r4[1];
                b[np * 2 + 1][0] = r4[2];
                b[np * 2 + 1][1] = r4[3];
            }
#pragma unroll
            for (int mt = 0; mt < 2; mt++)
#pragma unroll
                for (int nt = 0; nt < 4; nt++)
                    mma_tf32(acc[mt][nt], a[mt], b[nt][0], b[nt][1]);
        }
    };

    // ---- 3-stage mainloop: ONE barrier per chunk ----
    issue(0, 0);
    issue(1, 1);
    for (int it = 0; it < niter; it++) {
        CP_WAIT1();          // groups <= it complete (tail commits keep count)
        __syncthreads();     // chunk `it` visible; everyone left stage (it-1)%3
        if (it + 2 < niter) {
            issue(it + 2, (it + 2) % 3);   // = stage (it-1)%3, safe post-sync
        } else {
            CP_COMMIT();     // tail-race fix: keep committed count at it+2
        }
        compute(it % 3);
    }

    // ---------------- epilogue ----------------
    const int tg = t * 2;
#pragma unroll
    for (int mt = 0; mt < 2; mt++) {
#pragma unroll
        for (int h = 0; h < 2; h++) {
            const long r = m0 + m_w + mt * 16 + g + h * 8;
            if (r >= M) continue;
            float gt = 0.f;
            float g5[5];
            if (EPI == 3) gt = gate[r * (long)gld + zb];
            if (EPI == 4) {
                const float* gr = gate + r * 5;
#pragma unroll
                for (int q = 0; q < 5; q++) g5[q] = gr[q];
            }
#pragma unroll
            for (int nt = 0; nt < 4; nt++) {
                const int col = n_w + nt * 8 + tg;   // [0,128)
                float v0 = acc[mt][nt][h * 2 + 0];
                float v1 = acc[mt][nt][h * 2 + 1];
                if (EPI == 3) {
                    float2 bb = *(const float2*)(bias + n0 + col);
                    v0 = fmaxf(v0 + bb.x, 0.f) * gt;
                    v1 = fmaxf(v1 + bb.y, 0.f) * gt;
                } else if (EPI == 4) {
#pragma unroll
                    for (int q = 0; q < 5; q++) {
                        float2 bb = *(const float2*)(bias + q * 256 + n0 + col);
                        v0 += g5[q] * bb.x;
                        v1 += g5[q] * bb.y;
                    }
                }
                if constexpr (OUT_TF32) {
                    uint32_t* p = (uint32_t*)Cv + cbase + r * (long)ldc + n0 + col;
                    uint2 o;
                    o.x = f2tf32(v0);
                    o.y = f2tf32(v1);
                    *reinterpret_cast<uint2*>(p) = o;
                } else {
                    float* p = (float*)Cv + cbase + r * (long)ldc + n0 + col;
                    *reinterpret_cast<float2*>(p) = make_float2(v0, v1);
                }
            }
        }
    }
}

// ---------------------------------------------------------------------------
// in fp32 [z][R][C] -> out tf32: out[z*sOut + (c)*ldOut + r]   (C%32==0)
__global__ void trans_cvt_kernel(const float* __restrict__ src,
                                 uint32_t* __restrict__ dst,
                                 int R, int C, long sIn, long sOut, int ldOut)
{
    __shared__ float tbuf[32][33];
    const int r0 = blockIdx.x * 32, c0 = blockIdx.y * 32, z = blockIdx.z;
    const int tx = threadIdx.x, ty = threadIdx.y;
    const float* in = src + (long)z * sIn;
#pragma unroll
    for (int i = ty; i < 32; i += 8) {
        const int r = r0 + i;
        tbuf[i][tx] = (r < R) ? in[(long)r * C + c0 + tx] : 0.f;
    }
    __syncthreads();
    uint32_t* outp = dst + (long)z * sOut;
#pragma unroll
    for (int i = ty; i < 32; i += 8) {
        const int r = r0 + tx;
        if (r < R) outp[(long)(c0 + i) * ldOut + r] = f2tf32(tbuf[tx][i]);
    }
}

// out[b,n,0:256] = sum_s part[s][b][n][:]; out[b,n,256:512] = ori[b,n,:]
__global__ void finalize_kernel(const float* __restrict__ part,
                                const float* __restrict__ ori,
                                float* __restrict__ out, int total4)
{
    const int idx = blockIdx.x * blockDim.x + threadIdx.x;
    if (idx >= total4) return;
    const int d4 = idx & 63;
    const int bn = idx >> 6;
    const long stride4 = 4L * 2000 * 64;
    float4 s = ((const float4*)part)[idx];
#pragma unroll
    for (int sp = 1; sp < 4; sp++) {
        float4 v = ((const float4*)part)[idx + sp * stride4];
        s.x += v.x; s.y += v.y; s.z += v.z; s.w += v.w;
    }
    ((float4*)out)[(long)bn * 128 + d4] = s;
    float4 o = ((const float4*)ori)[idx];
    ((float4*)out)[(long)bn * 128 + 64 + d4] = o;
}

// ---------------------------------------------------------------------------
extern "C" void kernel_launch(void* const* d_in, const int* in_sizes, int n_in,
                              void* d_out, int out_size)
{
    const float* ed  = (const float*)d_in[0];   // [4,8000,5]
    const float* H   = (const float*)d_in[1];   // [4,8000,2000]
    const float* ori = (const float*)d_in[2];   // [4,2000,256]
    const float* W1  = (const float*)d_in[3];   // [5,256,128]
    const float* b1  = (const float*)d_in[4];   // [5,128]
    const float* W2  = (const float*)d_in[5];   // [5,128,256]
    const float* b2  = (const float*)d_in[6];   // [5,256]
    float* out = (float*)d_out;                 // [4,2000,512]

    uint32_t *oriT, *W1T, *W2cat, *edges, *htcat, *efT;
    float *ef, *part;
    cudaGetSymbolAddress((void**)&oriT, g_oriT);
    cudaGetSymbolAddress((void**)&W1T, g_W1T);
    cudaGetSymbolAddress((void**)&W2cat, g_W2cat);
    cudaGetSymbolAddress((void**)&edges, g_edges);
    cudaGetSymbolAddress((void**)&htcat, g_htcat);
    cudaGetSymbolAddress((void**)&ef, g_ef);
    cudaGetSymbolAddress((void**)&efT, g_efT);
    cudaGetSymbolAddress((void**)&part, g_part);

    const int SM_NT = 3 * (64 * 128 + 128 * 128);   // 73728
    const int SM_T  = 3 * (32 * 272 + 128 * 128);   // 75264
    cudaFuncSetAttribute(gemm_tf32<0, false, true, true>,
                         cudaFuncAttributeMaxDynamicSharedMemorySize, SM_NT);
    cudaFuncSetAttribute(gemm_tf32<3, false, false, true>,
                         cudaFuncAttributeMaxDynamicSharedMemorySize, SM_NT);
    cudaFuncSetAttribute(gemm_tf32<4, false, false, false>,
                         cudaFuncAttributeMaxDynamicSharedMemorySize, SM_NT);
    cudaFuncSetAttribute(gemm_tf32<0, true, true, false>,
                         cudaFuncAttributeMaxDynamicSharedMemorySize, SM_T);

    // 0) transpose+convert B operands
    trans_cvt_kernel<<<dim3(63, 8, 4), dim3(32, 8)>>>(
        ori, oriT, 2000, 256, 2000L * 256, 2000L * 256, 2000);
    trans_cvt_kernel<<<dim3(8, 4, 5), dim3(32, 8)>>>(
        W1, W1T, 256, 128, 256L * 128, 256L * 128, 256);
    // W2 [t][128 h][256 d] -> W2cat[d][t*128+h]  (ldOut=640, z offset = t*128)
    trans_cvt_kernel<<<dim3(4, 8, 5), dim3(32, 8)>>>(
        W2, W2cat, 128, 256, 128L * 256, 128, 640);

    // 1) edges = H @ ori   (A = H fp32 + in-loop cvt; B = oriT; tf32 out)
    gemm_tf32<0, false, true, true><<<dim3(125, 2, 4), 256, SM_NT>>>(
        (const uint32_t*)H, oriT, edges, 8000, 256, 2000,
        8000L * 2000, 256L * 2000, 8000L * 256, 0, 0, 0, 4,
        2000, 2000, 256, nullptr, 0, nullptr, 0);

    // 2a) MLP1 (z = t): htcat[:, t*128:(t+1)*128] = relu(edges@W1_t+b1_t)*gate_t
    gemm_tf32<3, false, false, true><<<dim3(500, 1, 5), 256, SM_NT>>>(
        edges, W1T, htcat, 32000, 128, 256,
        0, 128L * 256, 128 /* z col offset */, 0, 0, 0, 5,
        256, 256, 640, b1, 128, ed, 5);

    // 2b) fused MLP2: ef = htcat @ W2cat + sum_t gate_t*b2_t   (K=640, 1 launch)
    gemm_tf32<4, false, false, false><<<dim3(500, 2, 1), 256, SM_NT>>>(
        htcat, W2cat, ef, 32000, 256, 640,
        0, 0, 0, 0, 0, 0, 1,
        640, 640, 256, b2, 0, ed, 5);

    // 3) efT = transpose+convert(ef) per batch: [8000,256] -> [256,8000]
    trans_cvt_kernel<<<dim3(250, 8, 4), dim3(32, 8)>>>(
        ef, efT, 8000, 256, 8000L * 256, 256L * 8000, 8000);

    // 4) part[s] = H[ks]^T @ ef[ks]  (split-K x4; A = H fp32 TRANS + cvt)
    gemm_tf32<0, true, true, false><<<dim3(32, 2, 16), 256, SM_T>>>(
        (const uint32_t*)H, efT, part, 2000, 256, 2000,
        8000L * 2000, 256L * 8000, 2000L * 256,
        2000L * 2000, 2000, 4L * 2000 * 256, 4,
        2000, 8000, 256, nullptr, 0, nullptr, 0);

    // 5) out = [reduce(part), ori]
    finalize_kernel<<<(4 * 2000 * 64 + 255) / 256, 256>>>(
        part, ori, out, 4 * 2000 * 64);
}